// round 14
// baseline (speedup 1.0000x reference)
#include <cuda_runtime.h>
#include <cuda_fp16.h>
#include <math.h>
#include <stdint.h>

// Problem constants
#define RB 256      // batch
#define RT 512      // time steps
#define RH 1024     // hidden
#define RC 10       // classes

// Tiling: 8 batch groups (M=32) x 16 j-tiles (N=64) = 128 CTAs (1 per SM)
#define NM 8
#define NN 16
#define MT 32
#define NT 64
#define KH 512             // k per half (one per 8-warp warp-group)
#define NTHM 512           // 16 warps: (half = wid>>3, nq = wid&7)
#define NTH 256            // init/proj block size

// SMEM byte layout (dynamic)
#define W_PITCH 2064
#define SW_OFF 0                          // 64 rows x 2064 = 132096
#define SA_OFF 132096
// A chunk: 32 rows x 1040B (512 fp16 data + 16B pad)
#define A_PITCH 1040
#define A_BUF 33280                       // one half-chunk
#define SR_OFF (SA_OFF + 2 * A_BUF)       // 198656: reduction scratch
#define R_PITCH 48                        // 8 floats + 16B pad
#define R_TILE (32 * R_PITCH + 32)        // 1568 (stagger tiles by 32B)
#define SMEM_BYTES (SR_OFF + 16 * R_TILE) // 223744

// Persistent state (device globals; no allocation)
__device__ __half g_h[2][RB * RH];           // hidden state fp16, [b][k]
__device__ float g_xT[RT * RB];              // x transposed: [t][b]
__device__ unsigned int g_cnt[NM][2][32];    // per-(group, k-half) counters

// ----------------- helpers -----------------
__device__ __forceinline__ uint32_t smem_u32(const void* p) {
    uint32_t a;
    asm("{ .reg .u64 t; cvta.to.shared.u64 t, %1; cvt.u32.u64 %0, t; }"
        : "=r"(a) : "l"(p));
    return a;
}

__device__ __forceinline__ void ldsm4(uint32_t addr, uint32_t r[4]) {
    asm volatile("ldmatrix.sync.aligned.m8n8.x4.shared.b16 {%0,%1,%2,%3}, [%4];"
                 : "=r"(r[0]), "=r"(r[1]), "=r"(r[2]), "=r"(r[3]) : "r"(addr));
}

__device__ __forceinline__ void mma_f16(float* d, const uint32_t a[4],
                                        uint32_t b0, uint32_t b1) {
    asm volatile(
        "mma.sync.aligned.m16n8k16.row.col.f32.f16.f16.f32 "
        "{%0,%1,%2,%3},{%4,%5,%6,%7},{%8,%9},{%0,%1,%2,%3};"
        : "+f"(d[0]), "+f"(d[1]), "+f"(d[2]), "+f"(d[3])
        : "r"(a[0]), "r"(a[1]), "r"(a[2]), "r"(a[3]), "r"(b0), "r"(b1));
}

__device__ __forceinline__ void cp16(uint32_t d, const void* s) {
    asm volatile("cp.async.cg.shared.global [%0], [%1], 16;"
                 :: "r"(d), "l"(s) : "memory");
}

__device__ __forceinline__ uint32_t ld_acq(const unsigned int* p) {
    uint32_t v;
    asm volatile("ld.acquire.gpu.global.u32 %0, [%1];" : "=r"(v) : "l"(p)
                 : "memory");
    return v;
}
__device__ __forceinline__ void red_rel_add1(unsigned int* p) {
    asm volatile("red.release.gpu.global.add.u32 [%0], %1;"
                 :: "l"(p), "r"(1u) : "memory");
}
__device__ __forceinline__ void bar_sync(int id) {
    asm volatile("bar.sync %0, 256;" :: "r"(id) : "memory");
}

// Accurate tanh independent of fast-math lowering.
__device__ __forceinline__ float tanh_acc(float v) {
    float ax = fabsf(v);
    if (ax < 0.25f) {
        float s = v * v;
        float p = fmaf(s, 0.021869488f, -0.05396825397f);
        p = fmaf(s, p, 0.13333333333f);
        p = fmaf(s, p, -0.33333333333f);
        return fmaf(v * s, p, v);
    } else {
        float e = expf(-2.0f * ax);
        float r = (1.0f - e) / (1.0f + e);
        return copysignf(r, v);
    }
}

__global__ void __launch_bounds__(NTH, 1)
rnn_init_kernel(const float* __restrict__ x) {
    int idx = blockIdx.x * blockDim.x + threadIdx.x;
    if (idx < RB * RH) g_h[0][idx] = __float2half(0.0f);
    if (idx < RT * RB) {
        int b = idx & (RB - 1);
        int t = idx >> 8;
        g_xT[idx] = x[(size_t)b * RT + t];
    }
    if (idx < NM * 2 * 32) ((unsigned int*)g_cnt)[idx] = 0u;
}

__global__ void __launch_bounds__(NTHM, 1)
rnn_mma_kernel(const float* __restrict__ whx,
               const float* __restrict__ whh,
               const float* __restrict__ bias_h) {
    extern __shared__ char smem[];
    const uint32_t sb = smem_u32(smem);
    const uint32_t sw = sb + SW_OFF;

    const int tid = threadIdx.x;
    const int wid = tid >> 5;
    const int lane = tid & 31;
    const int lt = tid & 255;            // thread id within warp-group
    const int bid = blockIdx.x;
    const int m = bid >> 4;              // 0..7 batch group
    const int n = bid & 15;              // 0..15 j tile
    const int jg0 = n * NT;
    const int brow0 = m * MT;

    const int half = wid >> 3;           // 0..1 k-half
    const int nq = wid & 7;              // 0..7 n8 tile within CTA

    // whh slice (64 j rows x 1024 k) -> resident SMEM fp16, padded rows.
    for (int idx = tid; idx < NT * (RH / 2); idx += NTHM) {
        int jl = idx >> 9;                  // /512
        int k2 = (idx & 511) * 2;
        float2 wv = *reinterpret_cast<const float2*>(
            &whh[(size_t)(jg0 + jl) * RH + k2]);
        __half2 p2;
        p2.x = __float2half(wv.x);
        p2.y = __float2half(wv.y);
        uint32_t off = (uint32_t)jl * W_PITCH + (uint32_t)k2 * 2u;
        *reinterpret_cast<__half2*>(smem + SW_OFF + off) = p2;
    }

    // ldmatrix addresses
    const uint32_t abuf = sb + SA_OFF + (uint32_t)half * A_BUF;
    const uint32_t a_off = (uint32_t)(lane & 15) * A_PITCH +
                           (uint32_t)(lane >> 4) * 16u;
    // B x4 covers (n8, k32): lanes 0-7 j rows @k0, 8-15 @k8, 16-23 @k16, 24-31 @k24
    const uint32_t b_base = sw + ((uint32_t)nq * 8u + (uint32_t)(lane & 7)) * W_PITCH +
                            (uint32_t)(lane >> 3) * 16u +
                            (uint32_t)half * (KH * 2);

    // Reduction / epilogue constants: thread owns batch row (tid>>4),
    // j columns (tid&15)*4 .. +3.
    const int erow = tid >> 4;
    const int e4 = tid & 15;
    const int ecol = e4 * 4;
    const int nq_r = e4 >> 1;            // scratch tile to read
    const int co = (e4 & 1) * 16;        // byte offset within tile row
    float wx[4], bs[4];
#pragma unroll
    for (int i = 0; i < 4; ++i) {
        wx[i] = whx[jg0 + ecol + i];
        bs[i] = bias_h[jg0 + ecol + i];
    }
    const int fr = lane >> 2;            // fragment row within m16 (and +8)
    const int fc8 = (lane & 3) * 8;      // fragment col byte offset (float2)

    char* const srp = smem + SR_OFF;
    char* const wrp = srp + (half * 8 + nq) * R_TILE;
    const int barid = 1 + half;
    unsigned int* const pollp = &g_cnt[m][half][0];
    unsigned int* const relp = &g_cnt[m][n >> 3][0];

    __syncthreads();

    for (int t = 0; t < RT; ++t) {
        // ---- warp-group phase: poll own half, stage own chunk, MMA ----
        const __half* h = &g_h[t & 1][(size_t)brow0 * RH + half * KH];

        if (lt == 0) {
            const unsigned int need = 8u * (unsigned int)t;
            while (ld_acq(pollp) < need) { }
        }
        bar_sync(barid);

        // Stage 32x512 fp16 as two 16KB sub-chunks (256 threads each group).
#pragma unroll
        for (int sub = 0; sub < 2; ++sub) {
#pragma unroll
            for (int i = 0; i < 4; ++i) {
                int sp = lt + i * 256;          // 0..1023 segment within sub
                int row = sp >> 5;              // 32 segs per 512B half-row
                int c16 = sp & 31;
                uint32_t doff = (uint32_t)row * A_PITCH +
                                (uint32_t)sub * 512u + (uint32_t)c16 * 16u;
                const char* gs = (const char*)(h + (size_t)row * RH + sub * 256) +
                                 c16 * 16;
                cp16(abuf + doff, gs);
            }
            asm volatile("cp.async.commit_group;" ::: "memory");
        }

        float acc[8];
#pragma unroll
        for (int i = 0; i < 8; ++i) acc[i] = 0.f;

#pragma unroll
        for (int sub = 0; sub < 2; ++sub) {
            if (sub == 0) asm volatile("cp.async.wait_group 1;" ::: "memory");
            else          asm volatile("cp.async.wait_group 0;" ::: "memory");
            bar_sync(barid);

            const uint32_t so = (uint32_t)sub * 512u;
#pragma unroll
            for (int s = 0; s < 8; ++s) {       // 8 x k32
                uint32_t bf[4];
                ldsm4(b_base + so + (uint32_t)s * 64u, bf);
#pragma unroll
                for (int mt = 0; mt < 2; ++mt) {
                    uint32_t af[4];
                    const uint32_t am = abuf + a_off +
                        (uint32_t)(mt * 16) * A_PITCH + so + (uint32_t)s * 64u;
                    ldsm4(am, af);
                    mma_f16(acc + mt * 4, af, bf[0], bf[1]);
                    uint32_t af2[4];
                    ldsm4(am + 32u, af2);
                    mma_f16(acc + mt * 4, af2, bf[2], bf[3]);
                }
            }
        }

        // Write this warp's 32x8 partial tile to scratch.
#pragma unroll
        for (int mt = 0; mt < 2; ++mt) {
            const float* d = acc + mt * 4;
            int r = mt * 16 + fr;
            float2 v0; v0.x = d[0]; v0.y = d[1];
            float2 v1; v1.x = d[2]; v1.y = d[3];
            *reinterpret_cast<float2*>(wrp + r * R_PITCH + fc8) = v0;
            *reinterpret_cast<float2*>(wrp + (r + 8) * R_PITCH + fc8) = v1;
        }
        __syncthreads();

        // ---- full-CTA phase: 2-way reduce, epilogue, store, release ----
        const char* r0 = srp + nq_r * R_TILE + erow * R_PITCH + co;
        float4 p0 = *reinterpret_cast<const float4*>(r0);
        float4 p1 = *reinterpret_cast<const float4*>(r0 + 8 * R_TILE);
        float sum[4];
        sum[0] = p0.x + p1.x; sum[1] = p0.y + p1.y;
        sum[2] = p0.z + p1.z; sum[3] = p0.w + p1.w;

        float xb = g_xT[t * RB + brow0 + erow];
        const int ob = (t + 1) & 1;
        uint32_t pk[2];
#pragma unroll
        for (int q = 0; q < 2; ++q) {
            float a = tanh_acc(sum[2 * q] + fmaf(xb, wx[2 * q], bs[2 * q]));
            float b = tanh_acc(sum[2 * q + 1] + fmaf(xb, wx[2 * q + 1], bs[2 * q + 1]));
            __half2 p2;
            p2.x = __float2half(a);
            p2.y = __float2half(b);
            pk[q] = *reinterpret_cast<uint32_t*>(&p2);
        }
        {
            size_t po = (size_t)(brow0 + erow) * RH + jg0 + ecol;
            uint2 u; u.x = pk[0]; u.y = pk[1];
            *reinterpret_cast<uint2*>(&g_h[ob][po]) = u;
        }

        __syncthreads();          // h stores + scratch reads complete
        if (tid == 0) red_rel_add1(relp);
    }
}

// p[b][c] = h_final[b] . wph[c] + bias_p[c]; final h is in buffer 0 (RT even).
__global__ void __launch_bounds__(RB, 1)
rnn_proj_kernel(const float* __restrict__ wph,
                const float* __restrict__ bias_p,
                float* __restrict__ out) {
    const int c = blockIdx.x;    // 0..9
    const int b = threadIdx.x;   // 0..255
    const __half* h = &g_h[0][(size_t)b * RH];
    const float* w = wph + (size_t)c * RH;
    float a0 = 0.0f, a1 = 0.0f;
#pragma unroll 4
    for (int k = 0; k < RH; k += 2) {
        __half2 h2 = *reinterpret_cast<const __half2*>(h + k);
        a0 = fmaf(__half2float(h2.x), w[k], a0);
        a1 = fmaf(__half2float(h2.y), w[k + 1], a1);
    }
    out[b * RC + c] = a0 + a1 + bias_p[c];
}

extern "C" void kernel_launch(void* const* d_in, const int* in_sizes, int n_in,
                              void* d_out, int out_size) {
    (void)in_sizes; (void)n_in; (void)out_size;
    const float* x      = (const float*)d_in[0];   // [B, T]
    const float* whx    = (const float*)d_in[1];   // [H, 1]
    const float* whh    = (const float*)d_in[2];   // [H, H]
    const float* bias_h = (const float*)d_in[3];   // [H]
    const float* wph    = (const float*)d_in[4];   // [C, H]
    const float* bias_p = (const float*)d_in[5];   // [C]
    float* out = (float*)d_out;                    // [B, C]

    cudaFuncSetAttribute(rnn_mma_kernel,
                         cudaFuncAttributeMaxDynamicSharedMemorySize, SMEM_BYTES);

    rnn_init_kernel<<<(RB * RH + NTH - 1) / NTH, NTH>>>(x);
    rnn_mma_kernel<<<NM * NN, NTHM, SMEM_BYTES>>>(whx, whh, bias_h);
    rnn_proj_kernel<<<RC, RB>>>(wph, bias_p, out);
}

// round 15
// speedup vs baseline: 1.2063x; 1.2063x over previous
#include <cuda_runtime.h>
#include <cuda_fp16.h>
#include <math.h>
#include <stdint.h>

// Problem constants
#define RB 256      // batch
#define RT 512      // time steps
#define RH 1024     // hidden
#define RC 10       // classes

// Tiling: 8 batch groups (M=32) x 16 j-tiles (N=64) = 128 CTAs (1 per SM)
#define NM 8
#define NN 16
#define MT 32
#define NT 64
#define KH 512             // k per half (one chunk per warp-group)
#define NTH 256            // 8 warps: (half = wid>>2, nq = wid&3)

// SMEM byte layout (dynamic)
#define W_PITCH 2064
#define SW_OFF 0                          // 64 rows x 2064 = 132096
#define SA_OFF 132096
// A chunk: 32 rows x 1040B (512 fp16 data + 16B pad)
#define A_PITCH 1040
#define A_BUF 33280                       // one chunk (one per half)
#define SR_OFF (SA_OFF + 2 * A_BUF)       // 198656: reduction scratch
#define R_PITCH 80                        // 16 floats + 16B pad
#define R_TILE (32 * R_PITCH + 32)        // 2592 (stagger tiles by 32B)
#define SMEM_BYTES (SR_OFF + 8 * R_TILE)  // 219392

// Persistent state (device globals; no allocation)
__device__ __half g_h[2][RB * RH];           // hidden state fp16, [b][k]
__device__ float g_xT[RT * RB];              // x transposed: [t][b]
__device__ unsigned int g_cnt[NM][2][32];    // per-(group, k-half) counters

// ----------------- helpers -----------------
__device__ __forceinline__ uint32_t smem_u32(const void* p) {
    uint32_t a;
    asm("{ .reg .u64 t; cvta.to.shared.u64 t, %1; cvt.u32.u64 %0, t; }"
        : "=r"(a) : "l"(p));
    return a;
}

__device__ __forceinline__ void ldsm4(uint32_t addr, uint32_t r[4]) {
    asm volatile("ldmatrix.sync.aligned.m8n8.x4.shared.b16 {%0,%1,%2,%3}, [%4];"
                 : "=r"(r[0]), "=r"(r[1]), "=r"(r[2]), "=r"(r[3]) : "r"(addr));
}

__device__ __forceinline__ void mma_f16(float* d, const uint32_t a[4],
                                        uint32_t b0, uint32_t b1) {
    asm volatile(
        "mma.sync.aligned.m16n8k16.row.col.f32.f16.f16.f32 "
        "{%0,%1,%2,%3},{%4,%5,%6,%7},{%8,%9},{%0,%1,%2,%3};"
        : "+f"(d[0]), "+f"(d[1]), "+f"(d[2]), "+f"(d[3])
        : "r"(a[0]), "r"(a[1]), "r"(a[2]), "r"(a[3]), "r"(b0), "r"(b1));
}

__device__ __forceinline__ void cp16(uint32_t d, const void* s) {
    asm volatile("cp.async.cg.shared.global [%0], [%1], 16;"
                 :: "r"(d), "l"(s) : "memory");
}

__device__ __forceinline__ uint32_t ld_acq(const unsigned int* p) {
    uint32_t v;
    asm volatile("ld.acquire.gpu.global.u32 %0, [%1];" : "=r"(v) : "l"(p)
                 : "memory");
    return v;
}
__device__ __forceinline__ void red_rel_add1(unsigned int* p) {
    asm volatile("red.release.gpu.global.add.u32 [%0], %1;"
                 :: "l"(p), "r"(1u) : "memory");
}
__device__ __forceinline__ void bar_sync(int id) {
    asm volatile("bar.sync %0, 128;" :: "r"(id) : "memory");
}

// Accurate tanh independent of fast-math lowering.
__device__ __forceinline__ float tanh_acc(float v) {
    float ax = fabsf(v);
    if (ax < 0.25f) {
        float s = v * v;
        float p = fmaf(s, 0.021869488f, -0.05396825397f);
        p = fmaf(s, p, 0.13333333333f);
        p = fmaf(s, p, -0.33333333333f);
        return fmaf(v * s, p, v);
    } else {
        float e = expf(-2.0f * ax);
        float r = (1.0f - e) / (1.0f + e);
        return copysignf(r, v);
    }
}

__global__ void __launch_bounds__(NTH, 1)
rnn_init_kernel(const float* __restrict__ x) {
    int idx = blockIdx.x * blockDim.x + threadIdx.x;
    if (idx < RB * RH) g_h[0][idx] = __float2half(0.0f);
    if (idx < RT * RB) {
        int b = idx & (RB - 1);
        int t = idx >> 8;
        g_xT[idx] = x[(size_t)b * RT + t];
    }
    if (idx < NM * 2 * 32) ((unsigned int*)g_cnt)[idx] = 0u;
}

__global__ void __launch_bounds__(NTH, 1)
rnn_mma_kernel(const float* __restrict__ whx,
               const float* __restrict__ whh,
               const float* __restrict__ bias_h) {
    extern __shared__ char smem[];
    const uint32_t sb = smem_u32(smem);
    const uint32_t sw = sb + SW_OFF;

    const int tid = threadIdx.x;
    const int wid = tid >> 5;
    const int lane = tid & 31;
    const int lt = tid & 127;            // thread id within warp-group
    const int bid = blockIdx.x;
    const int m = bid >> 4;              // 0..7 batch group
    const int n = bid & 15;              // 0..15 j tile
    const int jg0 = n * NT;
    const int brow0 = m * MT;

    const int half = wid >> 2;           // 0..1 k-half (chunk)
    const int nq = wid & 3;              // 0..3 n16 tile within CTA

    // whh slice (64 j rows x 1024 k) -> resident SMEM fp16, padded rows.
    for (int idx = tid; idx < NT * (RH / 2); idx += NTH) {
        int jl = idx >> 9;                  // /512
        int k2 = (idx & 511) * 2;
        float2 wv = *reinterpret_cast<const float2*>(
            &whh[(size_t)(jg0 + jl) * RH + k2]);
        __half2 p2;
        p2.x = __float2half(wv.x);
        p2.y = __float2half(wv.y);
        uint32_t off = (uint32_t)jl * W_PITCH + (uint32_t)k2 * 2u;
        *reinterpret_cast<__half2*>(smem + SW_OFF + off) = p2;
    }

    // ldmatrix addresses
    const uint32_t abuf = sb + SA_OFF + (uint32_t)half * A_BUF;
    const uint32_t a_off = (uint32_t)(lane & 15) * A_PITCH +
                           (uint32_t)(lane >> 4) * 16u;
    const uint32_t b_row = (uint32_t)((lane & 7) + ((lane & 16) ? 8 : 0));
    const uint32_t b_base = sw + ((uint32_t)nq * 16u + b_row) * W_PITCH +
                            (uint32_t)((lane >> 3) & 1) * 16u +
                            (uint32_t)half * (KH * 2);

    // Reduction / epilogue constants: thread owns batch row (tid>>3),
    // j columns (tid&7)*8 .. +7.
    const int erow = tid >> 3;
    const int e8 = tid & 7;
    const int ecol = e8 * 8;
    const int nq_r = e8 >> 1;            // scratch tile to read
    const int co = (e8 & 1) * 32;        // byte offset within tile row
    float wx[8], bs[8];
#pragma unroll
    for (int i = 0; i < 8; ++i) {
        wx[i] = whx[jg0 + ecol + i];
        bs[i] = bias_h[jg0 + ecol + i];
    }
    const int fr = lane >> 2;            // fragment row within m16 (and +8)
    const int fc8 = (lane & 3) * 8;      // fragment col byte offset (float2)

    char* const srp = smem + SR_OFF;
    char* const wrp = srp + (half * 4 + nq) * R_TILE;
    const int barid = 1 + half;
    unsigned int* const pollp = &g_cnt[m][half][0];
    unsigned int* const relp = &g_cnt[m][n >> 3][0];

    __syncthreads();

    for (int t = 0; t < RT; ++t) {
        // ---- warp-group phase: per-warp poll, pipelined stage, MMA ----
        const __half* h = &g_h[t & 1][(size_t)brow0 * RH + half * KH];

        if (lane == 0) {
            const unsigned int need = 8u * (unsigned int)t;
            while (ld_acq(pollp) < need) { }
        }
        __syncwarp();

        // Stage 32x512 fp16 chunk as 4 sub-chunks of k128 (8KB each),
        // each committed separately for progressive consumption.
#pragma unroll
        for (int sub = 0; sub < 4; ++sub) {
#pragma unroll
            for (int i = 0; i < 4; ++i) {
                int sp = lt + i * 128;          // 0..511 segment within sub
                int row = sp >> 4;              // 16 segs per 256B sub-row
                int c16 = sp & 15;
                uint32_t doff = (uint32_t)row * A_PITCH +
                                (uint32_t)sub * 256u + (uint32_t)c16 * 16u;
                const char* gs = (const char*)(h + (size_t)row * RH +
                                               sub * 128) + c16 * 16;
                cp16(abuf + doff, gs);
            }
            asm volatile("cp.async.commit_group;" ::: "memory");
        }

        float acc[16];
#pragma unroll
        for (int i = 0; i < 16; ++i) acc[i] = 0.f;

#pragma unroll
        for (int sub = 0; sub < 4; ++sub) {
            // Own sub-chunks <= sub complete; bar makes it group-wide.
            if (sub == 0)      asm volatile("cp.async.wait_group 3;" ::: "memory");
            else if (sub == 1) asm volatile("cp.async.wait_group 2;" ::: "memory");
            else if (sub == 2) asm volatile("cp.async.wait_group 1;" ::: "memory");
            else               asm volatile("cp.async.wait_group 0;" ::: "memory");
            bar_sync(barid);

#pragma unroll
            for (int si = 0; si < 8; ++si) {    // 8 x k16 within sub
                const int s = sub * 8 + si;
                uint32_t bf[4];
                ldsm4(b_base + (uint32_t)s * 32u, bf);
#pragma unroll
                for (int mt = 0; mt < 2; ++mt) {
                    uint32_t af[4];
                    ldsm4(abuf + a_off + (uint32_t)(mt * 16) * A_PITCH +
                          (uint32_t)s * 32u, af);
                    mma_f16(acc + (mt * 2 + 0) * 4, af, bf[0], bf[1]);
                    mma_f16(acc + (mt * 2 + 1) * 4, af, bf[2], bf[3]);
                }
            }
        }

        // Write this warp's 32x16 partial tile to scratch.
#pragma unroll
        for (int mt = 0; mt < 2; ++mt) {
#pragma unroll
            for (int nt = 0; nt < 2; ++nt) {
                const float* d = acc + (mt * 2 + nt) * 4;
                int r = mt * 16 + fr;
                float2 v0; v0.x = d[0]; v0.y = d[1];
                float2 v1; v1.x = d[2]; v1.y = d[3];
                *reinterpret_cast<float2*>(wrp + r * R_PITCH + nt * 32 + fc8) = v0;
                *reinterpret_cast<float2*>(wrp + (r + 8) * R_PITCH + nt * 32 + fc8) = v1;
            }
        }
        __syncthreads();

        // ---- full-CTA phase: 2-way reduce, epilogue, store, release ----
        const char* r0 = srp + nq_r * R_TILE + erow * R_PITCH + co;
        float4 p00 = *reinterpret_cast<const float4*>(r0);
        float4 p01 = *reinterpret_cast<const float4*>(r0 + 16);
        const char* r1 = r0 + 4 * R_TILE;
        float4 p10 = *reinterpret_cast<const float4*>(r1);
        float4 p11 = *reinterpret_cast<const float4*>(r1 + 16);
        float sum[8];
        sum[0] = p00.x + p10.x; sum[1] = p00.y + p10.y;
        sum[2] = p00.z + p10.z; sum[3] = p00.w + p10.w;
        sum[4] = p01.x + p11.x; sum[5] = p01.y + p11.y;
        sum[6] = p01.z + p11.z; sum[7] = p01.w + p11.w;

        float xb = g_xT[t * RB + brow0 + erow];
        const int ob = (t + 1) & 1;
        uint32_t pk[4];
#pragma unroll
        for (int q = 0; q < 4; ++q) {
            float a = tanh_acc(sum[2 * q] + fmaf(xb, wx[2 * q], bs[2 * q]));
            float b = tanh_acc(sum[2 * q + 1] + fmaf(xb, wx[2 * q + 1], bs[2 * q + 1]));
            __half2 p2;
            p2.x = __float2half(a);
            p2.y = __float2half(b);
            pk[q] = *reinterpret_cast<uint32_t*>(&p2);
        }
        {
            size_t po = (size_t)(brow0 + erow) * RH + jg0 + ecol;
            uint4 u; u.x = pk[0]; u.y = pk[1]; u.z = pk[2]; u.w = pk[3];
            *reinterpret_cast<uint4*>(&g_h[ob][po]) = u;
        }

        __syncthreads();          // h stores + scratch reads complete
        if (tid == 0) red_rel_add1(relp);
    }
}

// p[b][c] = h_final[b] . wph[c] + bias_p[c]; final h is in buffer 0 (RT even).
__global__ void __launch_bounds__(RB, 1)
rnn_proj_kernel(const float* __restrict__ wph,
                const float* __restrict__ bias_p,
                float* __restrict__ out) {
    const int c = blockIdx.x;    // 0..9
    const int b = threadIdx.x;   // 0..255
    const __half* h = &g_h[0][(size_t)b * RH];
    const float* w = wph + (size_t)c * RH;
    float a0 = 0.0f, a1 = 0.0f;
#pragma unroll 4
    for (int k = 0; k < RH; k += 2) {
        __half2 h2 = *reinterpret_cast<const __half2*>(h + k);
        a0 = fmaf(__half2float(h2.x), w[k], a0);
        a1 = fmaf(__half2float(h2.y), w[k + 1], a1);
    }
    out[b * RC + c] = a0 + a1 + bias_p[c];
}

extern "C" void kernel_launch(void* const* d_in, const int* in_sizes, int n_in,
                              void* d_out, int out_size) {
    (void)in_sizes; (void)n_in; (void)out_size;
    const float* x      = (const float*)d_in[0];   // [B, T]
    const float* whx    = (const float*)d_in[1];   // [H, 1]
    const float* whh    = (const float*)d_in[2];   // [H, H]
    const float* bias_h = (const float*)d_in[3];   // [H]
    const float* wph    = (const float*)d_in[4];   // [C, H]
    const float* bias_p = (const float*)d_in[5];   // [C]
    float* out = (float*)d_out;                    // [B, C]

    cudaFuncSetAttribute(rnn_mma_kernel,
                         cudaFuncAttributeMaxDynamicSharedMemorySize, SMEM_BYTES);

    rnn_init_kernel<<<(RB * RH + NTH - 1) / NTH, NTH>>>(x);
    rnn_mma_kernel<<<NM * NN, NTH, SMEM_BYTES>>>(whx, whh, bias_h);
    rnn_proj_kernel<<<RC, RB>>>(wph, bias_p, out);
}